// round 14
// baseline (speedup 1.0000x reference)
#include <cuda_runtime.h>
#include <cuda_bf16.h>
#include <cuda_fp16.h>
#include <math.h>
#include <cstdint>

#define BB  8
#define CC  256
#define HH  64
#define WW  64
#define HWP 4096
#define NHH 4
#define HDD 64
#define C3  768
#define NPT 32

// ---- scratch (static device globals) ----
__device__ __nv_bfloat16  g_xfh[2ULL*BB*CC*HWP];   // msconv out, [c][n] bf16
__device__ __nv_bfloat16  g_wqkv[2ULL*C3*CC];      // BN-folded weights bf16
__device__ float          g_qb  [2ULL*C3];         // BN-folded bias
__device__ __nv_bfloat16  g_qk [2ULL*BB*512*HWP];
__device__ __half         g_vh [2ULL*BB*CC*HWP];
__device__ float g_ss_part[NPT*16*512];
__device__ float g_vs_part[NPT*16*256];
__device__ float g_rnorm[16*512];
__device__ float g_vmean[16*256];
__device__ float g_lpart[4ULL*2*BB*NHH*HDD*HDD];
__device__ float g_attn [2*BB*NHH*HDD*HDD];
__device__ float g_pool [2*BB*CC];
__device__ float g_gate [2*BB*CC];
__device__ __half g_Mh  [16ULL*CC*CC];

// ======================= helpers =======================
__device__ __forceinline__ uint32_t smem_u32(const void* p) {
    uint32_t a;
    asm("{ .reg .u64 t; cvta.to.shared.u64 t, %1; cvt.u32.u64 %0, t; }" : "=r"(a) : "l"(p));
    return a;
}
__device__ __forceinline__ void cpa16(uint32_t dst, const void* src) {
    asm volatile("cp.async.cg.shared.global [%0], [%1], 16;" :: "r"(dst), "l"(src));
}
#define CPA_COMMIT() asm volatile("cp.async.commit_group;" ::: "memory")
#define CPA_WAIT1()  asm volatile("cp.async.wait_group 1;" ::: "memory")
#define CPA_WAIT0()  asm volatile("cp.async.wait_group 0;" ::: "memory")

__device__ __forceinline__ void mma_bf16(float* d, const uint32_t* a, uint32_t b0, uint32_t b1) {
    asm volatile(
        "mma.sync.aligned.m16n8k16.row.col.f32.bf16.bf16.f32 "
        "{%0,%1,%2,%3}, {%4,%5,%6,%7}, {%8,%9}, {%0,%1,%2,%3};"
        : "+f"(d[0]), "+f"(d[1]), "+f"(d[2]), "+f"(d[3])
        : "r"(a[0]), "r"(a[1]), "r"(a[2]), "r"(a[3]), "r"(b0), "r"(b1));
}
__device__ __forceinline__ void mma_f16(float* d, const uint32_t* a, uint32_t b0, uint32_t b1) {
    asm volatile(
        "mma.sync.aligned.m16n8k16.row.col.f32.f16.f16.f32 "
        "{%0,%1,%2,%3}, {%4,%5,%6,%7}, {%8,%9}, {%0,%1,%2,%3};"
        : "+f"(d[0]), "+f"(d[1]), "+f"(d[2]), "+f"(d[3])
        : "r"(a[0]), "r"(a[1]), "r"(a[2]), "r"(a[3]), "r"(b0), "r"(b1));
}
__device__ __forceinline__ void ldsm_x4(uint32_t addr, uint32_t& r0, uint32_t& r1,
                                        uint32_t& r2, uint32_t& r3) {
    asm volatile("ldmatrix.sync.aligned.m8n8.x4.shared.b16 {%0,%1,%2,%3}, [%4];"
                 : "=r"(r0), "=r"(r1), "=r"(r2), "=r"(r3) : "r"(addr));
}
__device__ __forceinline__ void ldsm_x4_t(uint32_t addr, uint32_t& r0, uint32_t& r1,
                                          uint32_t& r2, uint32_t& r3) {
    asm volatile("ldmatrix.sync.aligned.m8n8.x4.trans.shared.b16 {%0,%1,%2,%3}, [%4];"
                 : "=r"(r0), "=r"(r1), "=r"(r2), "=r"(r3) : "r"(addr));
}
// fast GELU: tanh formulation with HW tanh.approx
__device__ __forceinline__ float gelu_f(float x) {
    float u = 0.7978845608028654f * fmaf(0.044715f * x, x * x, x);
    float th;
    asm("tanh.approx.f32 %0, %1;" : "=f"(th) : "f"(u));
    return 0.5f * x * (1.0f + th);
}

#define QST 72        // A smem row stride (elems): 144B
#define VST 136       // B/V smem row stride (elems): 272B, trans-ldmatrix friendly
#define SST 136       // qkv epilogue staging row stride (elems)

// ---------------------------------------------------------------------------
// K0a: fold BN into qkv weights + bias
// ---------------------------------------------------------------------------
__global__ void convert_w_kernel(
    const float* __restrict__ w1, const float* __restrict__ bq1,
    const float* __restrict__ g1, const float* __restrict__ be1,
    const float* __restrict__ m1, const float* __restrict__ v1,
    const float* __restrict__ w2, const float* __restrict__ bq2,
    const float* __restrict__ g2, const float* __restrict__ be2,
    const float* __restrict__ m2, const float* __restrict__ v2)
{
    int o = blockIdx.x, s = blockIdx.y;
    const float* W  = s ? w2  : w1;
    const float* bq = s ? bq2 : bq1;
    const float* bg = s ? g2  : g1;
    const float* bb = s ? be2 : be1;
    const float* bm = s ? m2  : m1;
    const float* bv = s ? v2  : v1;
    float scl = bg[o] * rsqrtf(bv[o] + 1e-5f);
    int c = threadIdx.x;
    g_wqkv[(size_t)s*C3*CC + (size_t)o*CC + c] = __float2bfloat16(W[(size_t)o*CC + c] * scl);
    if (c == 0)
        g_qb[s*C3 + o] = bq[o]*scl + bb[o] - bm[o]*scl;
}

// ---------------------------------------------------------------------------
// K1: fused multiscale depthwise conv on HFMA2 (half2 column pairs).
//     Two shifted half copies of the tile make every load a 4B-aligned LDS.32.
// ---------------------------------------------------------------------------
__global__ void msconv_kernel(const float* __restrict__ x1, const float* __restrict__ x2,
                              const float* __restrict__ w3, const float* __restrict__ b3,
                              const float* __restrict__ w5, const float* __restrict__ b5,
                              const float* __restrict__ w7, const float* __restrict__ b7)
{
    int c = blockIdx.x, b = blockIdx.y, s = blockIdx.z;
    const float* xin = (s ? x2 : x1) + ((size_t)b*CC + c)*HWP;

    __shared__ __align__(16) __half tA[70*70];
    __shared__ __align__(16) __half tB[70*70];   // tB[i] = tA[i+1]
    __shared__ __half2 wc2[49];
    int t = threadIdx.x;

    if (t < 49) {
        int ky = t / 7, kx = t % 7;
        float w = w7[c*49 + t];
        if (ky >= 1 && ky <= 5 && kx >= 1 && kx <= 5) w += w5[c*25 + (ky-1)*5 + (kx-1)];
        if (ky >= 2 && ky <= 4 && kx >= 2 && kx <= 4) w += w3[c*9  + (ky-2)*3 + (kx-2)];
        wc2[t] = __float2half2_rn(w * (1.0f/3.0f));
    }
    for (int i = t; i < 70*70; i += 256) {
        int ty = i / 70, tx = i % 70;
        int gy = ty - 3, gx = tx - 3;
        float v = (gy >= 0 && gy < HH && gx >= 0 && gx < WW) ? xin[gy*WW + gx] : 0.0f;
        __half h = __float2half(v);
        tA[i] = h;
        if (i > 0) tB[i-1] = h;
    }
    __syncthreads();

    int cp = t & 31, rg = t >> 5;
    int x0 = cp*2, y0 = rg*8;

    __half2 acc[8];
    #pragma unroll
    for (int p = 0; p < 8; p++) acc[p] = __float2half2_rn(0.0f);

    #pragma unroll
    for (int kx = 0; kx < 7; kx++) {
        __half2 pv[14];
        #pragma unroll
        for (int r = 0; r < 14; r++) {
            int idx = (y0 + r)*70 + x0 + kx;
            pv[r] = (kx & 1) ? *(const __half2*)(tB + idx - 1)
                             : *(const __half2*)(tA + idx);
        }
        #pragma unroll
        for (int ky = 0; ky < 7; ky++) {
            __half2 w = wc2[ky*7 + kx];
            #pragma unroll
            for (int p = 0; p < 8; p++)
                acc[p] = __hfma2(w, pv[p + ky], acc[p]);
        }
    }

    float bias = (b3[c] + b5[c] + b7[c]) * (1.0f/3.0f);
    __nv_bfloat16* outp = g_xfh + ((size_t)(s*BB+b)*CC + c)*HWP;
    #pragma unroll
    for (int p = 0; p < 8; p++) {
        float2 f = __half22float2(acc[p]);
        f.x += bias; f.y += bias;
        *(__nv_bfloat162*)(outp + (y0+p)*WW + x0) = __float22bfloat162_rn(f);
    }
}

// ---------------------------------------------------------------------------
// K2: qkv GEMM bf16 mma, BK=64, 3-stage ring / prefetch distance 2.
//     B loaded directly from [c][n] g_xfh via ldmatrix.trans.
// ---------------------------------------------------------------------------
__global__ void __launch_bounds__(256, 2) qkv_tc_kernel()
{
    __shared__ __align__(16) __nv_bfloat16 sA[3][128*QST];   // A: 128 o x 64 c
    __shared__ __align__(16) __nv_bfloat16 sB[3][64*VST];    // B: 64 c x 128 n
    __shared__ float sred[128][2];

    int oBase = blockIdx.x * 128;
    int pTile = blockIdx.y;
    int pBase = pTile * 128;
    int s = blockIdx.z >> 3, b = blockIdx.z & 7;
    int sb = s*BB + b;

    const __nv_bfloat16* W = g_wqkv + (size_t)s*C3*CC;
    const float* qb = g_qb + s*C3;
    const __nv_bfloat16* X = g_xfh + (size_t)sb*CC*HWP;   // [c][n]

    int t = threadIdx.x;
    int wid = t >> 5, lane = t & 31;
    int warpM = wid >> 1, warpN = wid & 1;
    int mbw = warpM*32, nbw = warpN*64;
    int g = lane >> 2, q = lane & 3;

    uint32_t sA0 = smem_u32(sA[0]);
    uint32_t sB0 = smem_u32(sB[0]);
    const uint32_t ABUF = 128*QST*2;
    const uint32_t BBUF = 64*VST*2;

    int lrow = lane & 7, lmat = lane >> 3;
    uint32_t aoff = (uint32_t)((mbw + (lmat & 1)*8 + lrow)*QST + (lmat >> 1)*8) * 2;
    uint32_t boff = (uint32_t)(((lmat & 1)*8 + lrow)*VST + nbw + (lmat >> 1)*8) * 2;

    float acc[2][8][4] = {};

    auto stage = [&](int k0, int st) {
        uint32_t ab = sA0 + st*ABUF, bb = sB0 + st*BBUF;
        #pragma unroll
        for (int e = 0; e < 4; e++) {
            int c = t + e*256;
            int arow = c >> 3, agrp = c & 7;
            cpa16(ab + (uint32_t)(arow*QST + agrp*8)*2,
                  W + (size_t)(oBase + arow)*CC + k0 + agrp*8);
            int brow = c >> 4, bgrp = c & 15;
            cpa16(bb + (uint32_t)(brow*VST + bgrp*8)*2,
                  X + (size_t)(k0 + brow)*HWP + pBase + bgrp*8);
        }
    };

    stage(0, 0);  CPA_COMMIT();
    stage(64, 1); CPA_COMMIT();

    const int NIT = CC / 64;   // 4
    for (int it = 0; it < NIT; it++) {
        if (it < NIT-1) CPA_WAIT1(); else CPA_WAIT0();
        __syncthreads();
        if (it + 2 < NIT) { stage((it+2)*64, (it+2)%3); CPA_COMMIT(); }

        int st = it % 3;
        uint32_t Ab = sA0 + st*ABUF, Bb = sB0 + st*BBUF;
        #pragma unroll
        for (int ks = 0; ks < 4; ks++) {
            uint32_t af[2][4];
            ldsm_x4(Ab + aoff + ks*32,        af[0][0], af[0][1], af[0][2], af[0][3]);
            ldsm_x4(Ab + aoff + 2304 + ks*32, af[1][0], af[1][1], af[1][2], af[1][3]);
            #pragma unroll
            for (int p = 0; p < 4; p++) {
                uint32_t r0, r1, r2, r3;
                ldsm_x4_t(Bb + boff + ks*(16*VST*2) + p*32, r0, r1, r2, r3);
                mma_bf16(acc[0][2*p],   af[0], r0, r1);
                mma_bf16(acc[0][2*p+1], af[0], r2, r3);
                mma_bf16(acc[1][2*p],   af[1], r0, r1);
                mma_bf16(acc[1][2*p+1], af[1], r2, r3);
            }
        }
    }

    bool isV = (oBase >= 512);
    float rs[2][2] = {};

    __syncthreads();
    char* stg = (char*)sA[0];

    #pragma unroll
    for (int mt = 0; mt < 2; mt++) {
        int r0l = mbw + mt*16 + g;
        int r1l = r0l + 8;
        float sft0 = qb[oBase + r0l], sft1 = qb[oBase + r1l];
        #pragma unroll
        for (int nt = 0; nt < 8; nt++) {
            int col = nbw + nt*8 + q*2;
            float2 v0, v1;
            v0.x = gelu_f(acc[mt][nt][0] + sft0);
            v0.y = gelu_f(acc[mt][nt][1] + sft0);
            v1.x = gelu_f(acc[mt][nt][2] + sft1);
            v1.y = gelu_f(acc[mt][nt][3] + sft1);
            uint32_t p0, p1;
            if (isV) {
                __half2 h0 = __float22half2_rn(v0), h1 = __float22half2_rn(v1);
                p0 = *(uint32_t*)&h0; p1 = *(uint32_t*)&h1;
                rs[mt][0] += v0.x + v0.y;
                rs[mt][1] += v1.x + v1.y;
            } else {
                __nv_bfloat162 b0 = __float22bfloat162_rn(v0), b1 = __float22bfloat162_rn(v1);
                p0 = *(uint32_t*)&b0; p1 = *(uint32_t*)&b1;
                rs[mt][0] += v0.x*v0.x + v0.y*v0.y;
                rs[mt][1] += v1.x*v1.x + v1.y*v1.y;
            }
            *(uint32_t*)(stg + (r0l*SST + col)*2) = p0;
            *(uint32_t*)(stg + (r1l*SST + col)*2) = p1;
        }
    }

    #pragma unroll
    for (int mt = 0; mt < 2; mt++)
        #pragma unroll
        for (int rr = 0; rr < 2; rr++) {
            float v = rs[mt][rr];
            v += __shfl_xor_sync(0xffffffffu, v, 1);
            v += __shfl_xor_sync(0xffffffffu, v, 2);
            if (q == 0) sred[mbw + mt*16 + g + rr*8][warpN] = v;
        }
    __syncthreads();

    #pragma unroll
    for (int e = 0; e < 8; e++) {
        int c = t + e*256;
        int row = c >> 4, grp = c & 15;
        uint4 val = *(uint4*)(stg + (row*SST + grp*8)*2);
        if (isV)
            *(uint4*)(g_vh + ((size_t)sb*CC + (oBase - 512 + row))*HWP + pBase + grp*8) = val;
        else
            *(uint4*)(g_qk + ((size_t)sb*512 + oBase + row)*HWP + pBase + grp*8) = val;
    }

    if (t < 128) {
        float tot = sred[t][0] + sred[t][1];
        if (isV) g_vs_part[((size_t)pTile*16 + sb)*256 + (oBase - 512 + t)] = tot;
        else     g_ss_part[((size_t)pTile*16 + sb)*512 + (oBase + t)] = tot;
    }
}

// ---------------------------------------------------------------------------
// K3: finalize rnorm and vmean from partials
// ---------------------------------------------------------------------------
__global__ void finalize_kernel() {
    int sb = blockIdx.x;
    int t = threadIdx.x;
    float ss = 0.0f;
    for (int p = 0; p < NPT; p++) ss += g_ss_part[((size_t)p*16 + sb)*512 + t];
    g_rnorm[sb*512 + t] = 1.0f / fmaxf(sqrtf(ss), 1e-12f);
    if (t < 256) {
        float vs = 0.0f;
        for (int p = 0; p < NPT; p++) vs += g_vs_part[((size_t)p*16 + sb)*256 + t];
        g_vmean[sb*256 + t] = vs * (1.0f/HWP);
    }
}

// ---------------------------------------------------------------------------
// K4: attention logit partials via bf16 mma + ldmatrix
// ---------------------------------------------------------------------------
#define ANC 128
#define AST (ANC + 8)

__global__ void __launch_bounds__(256) attn_part_kernel() {
    int cx = blockIdx.x;
    int hb = blockIdx.y;
    int which = blockIdx.z;
    int h = hb & 3, b = hb >> 2;
    const __nv_bfloat16* Q = g_qk + ((size_t)(which*BB+b)*512 +       h*HDD)*HWP;
    const __nv_bfloat16* K = g_qk + ((size_t)((1-which)*BB+b)*512 + 256 + h*HDD)*HWP;

    __shared__ __align__(16) __nv_bfloat16 sQ[2][64*AST];
    __shared__ __align__(16) __nv_bfloat16 sK[2][64*AST];

    int t = threadIdx.x;
    int wid = t >> 5, lane = t & 31;
    int g = lane >> 2, q = lane & 3;
    int dBase = wid * 8;

    uint32_t sQb[2] = { smem_u32(sQ[0]), smem_u32(sQ[1]) };
    uint32_t sKb[2] = { smem_u32(sK[0]), smem_u32(sK[1]) };

    int lrow = lane & 7, lmat = lane >> 3;
    uint32_t qoff = (uint32_t)(((lmat & 1)*8 + lrow)*AST + (lmat >> 1)*8) * 2;
    uint32_t koff = (uint32_t)((dBase + lrow)*AST + lmat*8) * 2;

    auto stage = [&](int n0, int buf) {
        #pragma unroll
        for (int e = 0; e < 4; e++) {
            int c = t + e*256;
            int row = c >> 4, grp = c & 15;
            cpa16(sQb[buf] + (uint32_t)(row*AST + grp*8)*2, Q + (size_t)row*HWP + n0 + grp*8);
            cpa16(sKb[buf] + (uint32_t)(row*AST + grp*8)*2, K + (size_t)row*HWP + n0 + grp*8);
        }
    };

    float acc[4][4] = {};
    int n0base = cx * 1024;

    stage(n0base, 0);
    CPA_COMMIT();

    for (int st = 0; st < 8; st++) {
        int buf = st & 1;
        if (st + 1 < 8) { stage(n0base + (st+1)*ANC, buf ^ 1); CPA_COMMIT(); CPA_WAIT1(); }
        else CPA_WAIT0();
        __syncthreads();

        uint32_t Qb = sQb[buf], Kb = sKb[buf];
        #pragma unroll
        for (int ks2 = 0; ks2 < 4; ks2++) {
            uint32_t kb0, kb1, kb2, kb3;
            ldsm_x4(Kb + koff + ks2*64, kb0, kb1, kb2, kb3);
            #pragma unroll
            for (int half = 0; half < 2; half++) {
                uint32_t b0 = half ? kb2 : kb0;
                uint32_t b1 = half ? kb3 : kb1;
                #pragma unroll
                for (int mt = 0; mt < 4; mt++) {
                    uint32_t a[4];
                    ldsm_x4(Qb + qoff + mt*(16*AST*2) + ks2*64 + half*32,
                            a[0], a[1], a[2], a[3]);
                    mma_bf16(acc[mt], a, b0, b1);
                }
            }
        }
        __syncthreads();
    }

    float* P = g_lpart + (size_t)(((cx*2 + which)*BB + b)*NHH + h)*HDD*HDD;
    #pragma unroll
    for (int mt = 0; mt < 4; mt++) {
        float2 lo = { acc[mt][0], acc[mt][1] };
        float2 hi = { acc[mt][2], acc[mt][3] };
        *(float2*)(P + (mt*16 + g)*64 + dBase + 2*q) = lo;
        *(float2*)(P + (mt*16 + g + 8)*64 + dBase + 2*q) = hi;
    }
}

// ---------------------------------------------------------------------------
// K5: softmax over summed partials + SE-pool via A @ vmean (256 threads)
// ---------------------------------------------------------------------------
__global__ void __launch_bounds__(256) attn_soft_kernel() {
    int hb = blockIdx.x;
    int which = blockIdx.y;
    int h = hb & 3, b = hb >> 2;
    int t = threadIdx.x;

    __shared__ float S[64][65];
    __shared__ float rq[64], rk[64], vm[64];

    if (t < 64) {
        rq[t] = g_rnorm[(which*BB+b)*512 +       h*64 + t];
        rk[t] = g_rnorm[((1-which)*BB+b)*512 + 256 + h*64 + t];
        vm[t] = g_vmean[(which*BB+b)*256 + h*64 + t];
    }

    float vacc[16];
    {
        const float* P0 = g_lpart + (size_t)(((0*2 + which)*BB + b)*NHH + h)*HDD*HDD;
        #pragma unroll
        for (int j = 0; j < 16; j++) vacc[j] = P0[t + j*256];
    }
    #pragma unroll
    for (int cx = 1; cx < 4; cx++) {
        const float* P = g_lpart + (size_t)(((cx*2 + which)*BB + b)*NHH + h)*HDD*HDD;
        #pragma unroll
        for (int j = 0; j < 16; j++) vacc[j] += P[t + j*256];
    }
    #pragma unroll
    for (int j = 0; j < 16; j++) {
        int idx = t + j*256;
        S[idx >> 6][idx & 63] = vacc[j];
    }
    __syncthreads();

    if (t < 64) {
        float sc = 0.125f * rq[t];
        float m = -1e30f;
        #pragma unroll
        for (int d = 0; d < 64; d++) {
            float v = S[t][d] * sc * rk[d];
            S[t][d] = v;
            m = fmaxf(m, v);
        }
        float sum = 0.0f;
        #pragma unroll
        for (int d = 0; d < 64; d++) { float ev = expf(S[t][d] - m); S[t][d] = ev; sum += ev; }
        float inv = 1.0f / sum;

        float* ap = g_attn + (size_t)(((which*BB+b)*NHH + h)*HDD + t)*HDD;
        float pool = 0.0f;
        #pragma unroll
        for (int d = 0; d < 64; d++) {
            float a = S[t][d] * inv;
            ap[d] = a;
            pool += a * vm[d];
        }
        g_pool[(which*BB+b)*CC + h*64 + t] = pool;
    }
}

// ---------------------------------------------------------------------------
// K6: SE gate
// ---------------------------------------------------------------------------
__global__ void se_kernel(const float* __restrict__ w1, const float* __restrict__ b1_,
                          const float* __restrict__ w2, const float* __restrict__ b2_)
{
    int b = blockIdx.x, s = blockIdx.y;
    __shared__ float pm[256], ys[32];
    int t = threadIdx.x;
    pm[t] = g_pool[(s*BB+b)*CC + t];
    __syncthreads();
    if (t < 32) {
        float a = b1_[t];
        #pragma unroll 8
        for (int c = 0; c < 256; c++) a += w1[t*256 + c]*pm[c];
        ys[t] = fmaxf(a, 0.0f);
    }
    __syncthreads();
    float a = b2_[t];
    #pragma unroll
    for (int r = 0; r < 32; r++) a += w2[t*32 + r]*ys[r];
    g_gate[(s*BB+b)*CC + t] = 1.0f/(1.0f + expf(-a));
}

// ---------------------------------------------------------------------------
// K7: M = PO * diag(gate) * A_blk  -> fp16
// ---------------------------------------------------------------------------
__global__ void __launch_bounds__(256) mproj_kernel(
    const float* __restrict__ pw1, const float* __restrict__ pw2)
{
    int h = blockIdx.x, b = blockIdx.y, s = blockIdx.z;
    int sb = s*BB + b;
    const float* PO = s ? pw2 : pw1;
    const float* A  = g_attn + (size_t)((sb)*NHH + h)*HDD*HDD;
    int t = threadIdx.x;

    __shared__ float Ag[64][65];
    __shared__ float gsl[64];

    if (t < 64) gsl[t] = g_gate[sb*CC + h*64 + t];
    for (int idx = t; idx < 4096; idx += 256)
        Ag[idx >> 6][idx & 63] = A[idx];
    __syncthreads();

    float m[64];
    #pragma unroll
    for (int d = 0; d < 64; d++) m[d] = 0.0f;

    const float* po = PO + (size_t)t*CC + h*64;
    for (int c = 0; c < 64; c++) {
        float poc = po[c] * gsl[c];
        #pragma unroll
        for (int d = 0; d < 64; d++) m[d] += poc * Ag[c][d];
    }

    __half* Mp = g_Mh + (size_t)sb*CC*CC + (size_t)t*CC + h*64;
    #pragma unroll
    for (int d = 0; d < 64; d += 2)
        *(__half2*)(Mp + d) = __floats2half2_rn(m[d], m[d+1]);
}

// ---------------------------------------------------------------------------
// K8: out = M @ V + bias + residual  (fp16 mma; BK=64, 3-stage ring)
// ---------------------------------------------------------------------------
__global__ void __launch_bounds__(256, 2) mv_tc_kernel(
    const float* __restrict__ x1, const float* __restrict__ x2,
    const float* __restrict__ pb1, const float* __restrict__ pb2,
    float* __restrict__ out)
{
    __shared__ __align__(16) __half sM[3][128*QST];
    __shared__ __align__(16) __half sV[3][64*VST];

    int pBase = blockIdx.x * 128;
    int oBase = blockIdx.y * 128;
    int s = blockIdx.z >> 3, b = blockIdx.z & 7;
    int sb = s*BB + b;

    const __half* Mh = g_Mh + (size_t)sb*CC*CC;
    const __half* Vh = g_vh + (size_t)sb*CC*HWP;
    const float* pb  = s ? pb2 : pb1;
    const float* res = (s ? x2 : x1) + (size_t)b*CC*HWP;
    float*       Y   = out + ((size_t)sb)*CC*HWP;

    int t = threadIdx.x;
    int wid = t >> 5, lane = t & 31;
    int warpM = wid >> 1, warpN = wid & 1;
    int mbw = warpM*32, nbw = warpN*64;
    int g = lane >> 2, q = lane & 3;
    int lrow = lane & 7, lmat = lane >> 3;

    uint32_t sM0 = smem_u32(sM[0]);
    uint32_t sV0 = smem_u32(sV[0]);
    const uint32_t MBUF = 128*QST*2;
    const uint32_t VBUF = 64*VST*2;

    uint32_t aoff = (uint32_t)((mbw + (lmat & 1)*8 + lrow)*QST + (lmat >> 1)*8) * 2;
    uint32_t boff = (uint32_t)(((lmat & 1)*8 + lrow)*VST + nbw + (lmat >> 1)*8) * 2;

    float acc[2][8][4] = {};

    auto stage = [&](int k0, int st) {
        uint32_t ab = sM0 + st*MBUF, vb = sV0 + st*VBUF;
        #pragma unroll
        for (int e = 0; e < 4; e++) {
            int c = t + e*256;
            int mrow = c >> 3, mgrp = c & 7;
            cpa16(ab + (uint32_t)(mrow*QST + mgrp*8)*2,
                  Mh + (size_t)(oBase + mrow)*CC + k0 + mgrp*8);
            int vrow = c >> 4, vgrp = c & 15;
            cpa16(vb + (uint32_t)(vrow*VST + vgrp*8)*2,
                  Vh + (size_t)(k0 + vrow)*HWP + pBase + vgrp*8);
        }
    };

    stage(0, 0);  CPA_COMMIT();
    stage(64, 1); CPA_COMMIT();

    const int NIT = CC / 64;   // 4
    for (int it = 0; it < NIT; it++) {
        if (it < NIT-1) CPA_WAIT1(); else CPA_WAIT0();
        __syncthreads();
        if (it + 2 < NIT) { stage((it+2)*64, (it+2)%3); CPA_COMMIT(); }

        int st = it % 3;
        uint32_t Ab = sM0 + st*MBUF, Vb = sV0 + st*VBUF;
        #pragma unroll
        for (int ks = 0; ks < 4; ks++) {
            uint32_t af[2][4];
            ldsm_x4(Ab + aoff + ks*32,        af[0][0], af[0][1], af[0][2], af[0][3]);
            ldsm_x4(Ab + aoff + 2304 + ks*32, af[1][0], af[1][1], af[1][2], af[1][3]);
            #pragma unroll
            for (int p = 0; p < 4; p++) {
                uint32_t r0, r1, r2, r3;
                ldsm_x4_t(Vb + boff + ks*(16*VST*2) + p*32, r0, r1, r2, r3);
                mma_f16(acc[0][2*p],   af[0], r0, r1);
                mma_f16(acc[0][2*p+1], af[0], r2, r3);
                mma_f16(acc[1][2*p],   af[1], r0, r1);
                mma_f16(acc[1][2*p+1], af[1], r2, r3);
            }
        }
    }

    #pragma unroll
    for (int mt = 0; mt < 2; mt++) {
        int o0 = oBase + mbw + mt*16 + g;
        int o1 = o0 + 8;
        float bo0 = pb[o0], bo1 = pb[o1];
        float* y0 = Y + (size_t)o0*HWP + pBase + nbw + q*2;
        float* y1 = Y + (size_t)o1*HWP + pBase + nbw + q*2;
        const float* r0 = res + (size_t)o0*HWP + pBase + nbw + q*2;
        const float* r1 = res + (size_t)o1*HWP + pBase + nbw + q*2;
        #pragma unroll
        for (int nt = 0; nt < 8; nt++) {
            float2 rv0 = *(const float2*)(r0 + nt*8);
            float2 rv1 = *(const float2*)(r1 + nt*8);
            float2 v0, v1;
            v0.x = acc[mt][nt][0] + bo0 + rv0.x;
            v0.y = acc[mt][nt][1] + bo0 + rv0.y;
            v1.x = acc[mt][nt][2] + bo1 + rv1.x;
            v1.y = acc[mt][nt][3] + bo1 + rv1.y;
            *(float2*)(y0 + nt*8) = v0;
            *(float2*)(y1 + nt*8) = v1;
        }
    }
}

// ---------------------------------------------------------------------------
extern "C" void kernel_launch(void* const* d_in, const int* in_sizes, int n_in,
                              void* d_out, int out_size)
{
    const float* x1     = (const float*)d_in[0];
    const float* x2     = (const float*)d_in[1];
    const float* ms_w3  = (const float*)d_in[2];
    const float* ms_b3  = (const float*)d_in[3];
    const float* ms_w5  = (const float*)d_in[4];
    const float* ms_b5  = (const float*)d_in[5];
    const float* ms_w7  = (const float*)d_in[6];
    const float* ms_b7  = (const float*)d_in[7];
    const float* qkv1_w = (const float*)d_in[8];
    const float* qkv1_b = (const float*)d_in[9];
    const float* bn1_g  = (const float*)d_in[10];
    const float* bn1_b  = (const float*)d_in[11];
    const float* bn1_m  = (const float*)d_in[12];
    const float* bn1_v  = (const float*)d_in[13];
    const float* qkv2_w = (const float*)d_in[14];
    const float* qkv2_b = (const float*)d_in[15];
    const float* bn2_g  = (const float*)d_in[16];
    const float* bn2_b  = (const float*)d_in[17];
    const float* bn2_m  = (const float*)d_in[18];
    const float* bn2_v  = (const float*)d_in[19];
    const float* ca_w1  = (const float*)d_in[20];
    const float* ca_b1  = (const float*)d_in[21];
    const float* ca_w2  = (const float*)d_in[22];
    const float* ca_b2  = (const float*)d_in[23];
    const float* po1_w  = (const float*)d_in[24];
    const float* po1_b  = (const float*)d_in[25];
    const float* po2_w  = (const float*)d_in[26];
    const float* po2_b  = (const float*)d_in[27];
    float* out = (float*)d_out;

    convert_w_kernel<<<dim3(C3, 2), 256>>>(
        qkv1_w, qkv1_b, bn1_g, bn1_b, bn1_m, bn1_v,
        qkv2_w, qkv2_b, bn2_g, bn2_b, bn2_m, bn2_v);
    msconv_kernel<<<dim3(CC, BB, 2), 256>>>(x1, x2, ms_w3, ms_b3, ms_w5, ms_b5, ms_w7, ms_b7);
    qkv_tc_kernel<<<dim3(C3/128, NPT, 16), 256>>>();
    finalize_kernel<<<16, 512>>>();
    attn_part_kernel<<<dim3(4, NHH*BB, 2), 256>>>();
    attn_soft_kernel<<<dim3(NHH*BB, 2), 256>>>();
    se_kernel<<<dim3(BB, 2), 256>>>(ca_w1, ca_b1, ca_w2, ca_b2);
    mproj_kernel<<<dim3(NHH, BB, 2), 256>>>(po1_w, po2_w);
    mv_tc_kernel<<<dim3(HWP/128, CC/128, 16), 256>>>(x1, x2, po1_b, po2_b, out);
}

// round 15
// speedup vs baseline: 1.0839x; 1.0839x over previous
#include <cuda_runtime.h>
#include <cuda_bf16.h>
#include <cuda_fp16.h>
#include <math.h>
#include <cstdint>

#define BB  8
#define CC  256
#define HH  64
#define WW  64
#define HWP 4096
#define NHH 4
#define HDD 64
#define C3  768
#define NPT 32

// ---- scratch (static device globals) ----
__device__ __nv_bfloat16  g_xfh[2ULL*BB*CC*HWP];   // msconv out, [c][n] bf16
__device__ __nv_bfloat16  g_wqkv[2ULL*C3*CC];      // BN-folded weights bf16
__device__ float          g_qb  [2ULL*C3];         // BN-folded bias
__device__ __nv_bfloat16  g_qk [2ULL*BB*512*HWP];
__device__ __half         g_vh [2ULL*BB*CC*HWP];
__device__ float g_ss_part[NPT*16*512];
__device__ float g_vs_part[NPT*16*256];
__device__ float g_lpart[4ULL*2*BB*NHH*HDD*HDD];
__device__ float g_attn [2*BB*NHH*HDD*HDD];
__device__ float g_pool [2*BB*CC];
__device__ __half g_Mh  [16ULL*CC*CC];

// ======================= helpers =======================
__device__ __forceinline__ uint32_t smem_u32(const void* p) {
    uint32_t a;
    asm("{ .reg .u64 t; cvta.to.shared.u64 t, %1; cvt.u32.u64 %0, t; }" : "=r"(a) : "l"(p));
    return a;
}
__device__ __forceinline__ void cpa16(uint32_t dst, const void* src) {
    asm volatile("cp.async.cg.shared.global [%0], [%1], 16;" :: "r"(dst), "l"(src));
}
#define CPA_COMMIT() asm volatile("cp.async.commit_group;" ::: "memory")
#define CPA_WAIT1()  asm volatile("cp.async.wait_group 1;" ::: "memory")
#define CPA_WAIT0()  asm volatile("cp.async.wait_group 0;" ::: "memory")

__device__ __forceinline__ void mma_bf16(float* d, const uint32_t* a, uint32_t b0, uint32_t b1) {
    asm volatile(
        "mma.sync.aligned.m16n8k16.row.col.f32.bf16.bf16.f32 "
        "{%0,%1,%2,%3}, {%4,%5,%6,%7}, {%8,%9}, {%0,%1,%2,%3};"
        : "+f"(d[0]), "+f"(d[1]), "+f"(d[2]), "+f"(d[3])
        : "r"(a[0]), "r"(a[1]), "r"(a[2]), "r"(a[3]), "r"(b0), "r"(b1));
}
__device__ __forceinline__ void mma_f16(float* d, const uint32_t* a, uint32_t b0, uint32_t b1) {
    asm volatile(
        "mma.sync.aligned.m16n8k16.row.col.f32.f16.f16.f32 "
        "{%0,%1,%2,%3}, {%4,%5,%6,%7}, {%8,%9}, {%0,%1,%2,%3};"
        : "+f"(d[0]), "+f"(d[1]), "+f"(d[2]), "+f"(d[3])
        : "r"(a[0]), "r"(a[1]), "r"(a[2]), "r"(a[3]), "r"(b0), "r"(b1));
}
__device__ __forceinline__ void ldsm_x4(uint32_t addr, uint32_t& r0, uint32_t& r1,
                                        uint32_t& r2, uint32_t& r3) {
    asm volatile("ldmatrix.sync.aligned.m8n8.x4.shared.b16 {%0,%1,%2,%3}, [%4];"
                 : "=r"(r0), "=r"(r1), "=r"(r2), "=r"(r3) : "r"(addr));
}
__device__ __forceinline__ void ldsm_x4_t(uint32_t addr, uint32_t& r0, uint32_t& r1,
                                          uint32_t& r2, uint32_t& r3) {
    asm volatile("ldmatrix.sync.aligned.m8n8.x4.trans.shared.b16 {%0,%1,%2,%3}, [%4];"
                 : "=r"(r0), "=r"(r1), "=r"(r2), "=r"(r3) : "r"(addr));
}
// fast GELU: tanh formulation with HW tanh.approx
__device__ __forceinline__ float gelu_f(float x) {
    float u = 0.7978845608028654f * fmaf(0.044715f * x, x * x, x);
    float th;
    asm("tanh.approx.f32 %0, %1;" : "=f"(th) : "f"(u));
    return 0.5f * x * (1.0f + th);
}

#define QST 72        // A smem row stride (elems): 144B
#define VST 136       // B/V smem row stride (elems): 272B, trans-ldmatrix friendly
#define SST 136       // qkv epilogue staging row stride (elems)

// ---------------------------------------------------------------------------
// K0a: fold BN into qkv weights + bias
// ---------------------------------------------------------------------------
__global__ void convert_w_kernel(
    const float* __restrict__ w1, const float* __restrict__ bq1,
    const float* __restrict__ g1, const float* __restrict__ be1,
    const float* __restrict__ m1, const float* __restrict__ v1,
    const float* __restrict__ w2, const float* __restrict__ bq2,
    const float* __restrict__ g2, const float* __restrict__ be2,
    const float* __restrict__ m2, const float* __restrict__ v2)
{
    int o = blockIdx.x, s = blockIdx.y;
    const float* W  = s ? w2  : w1;
    const float* bq = s ? bq2 : bq1;
    const float* bg = s ? g2  : g1;
    const float* bb = s ? be2 : be1;
    const float* bm = s ? m2  : m1;
    const float* bv = s ? v2  : v1;
    float scl = bg[o] * rsqrtf(bv[o] + 1e-5f);
    int c = threadIdx.x;
    g_wqkv[(size_t)s*C3*CC + (size_t)o*CC + c] = __float2bfloat16(W[(size_t)o*CC + c] * scl);
    if (c == 0)
        g_qb[s*C3 + o] = bq[o]*scl + bb[o] - bm[o]*scl;
}

// ---------------------------------------------------------------------------
// K1: fused multiscale depthwise conv; writes bf16 [c][n]   (R13 fp32 version)
// ---------------------------------------------------------------------------
__global__ void msconv_kernel(const float* __restrict__ x1, const float* __restrict__ x2,
                              const float* __restrict__ w3, const float* __restrict__ b3,
                              const float* __restrict__ w5, const float* __restrict__ b5,
                              const float* __restrict__ w7, const float* __restrict__ b7)
{
    int c = blockIdx.x, b = blockIdx.y, s = blockIdx.z;
    const float* xin = (s ? x2 : x1) + ((size_t)b*CC + c)*HWP;

    __shared__ float tile[70*70];
    __shared__ float wc[49];
    int t = threadIdx.x;

    if (t < 49) {
        int ky = t / 7, kx = t % 7;
        float w = w7[c*49 + t];
        if (ky >= 1 && ky <= 5 && kx >= 1 && kx <= 5) w += w5[c*25 + (ky-1)*5 + (kx-1)];
        if (ky >= 2 && ky <= 4 && kx >= 2 && kx <= 4) w += w3[c*9  + (ky-2)*3 + (kx-2)];
        wc[t] = w * (1.0f/3.0f);
    }
    for (int i = t; i < 70*70; i += 256) {
        int ty = i / 70, tx = i % 70;
        int gy = ty - 3, gx = tx - 3;
        tile[i] = (gy >= 0 && gy < HH && gx >= 0 && gx < WW) ? xin[gy*WW + gx] : 0.0f;
    }
    __syncthreads();

    int tx = t & 63;
    int ty0 = (t >> 6) * 16;
    float bias = (b3[c] + b5[c] + b7[c]) * (1.0f/3.0f);

    float acc[16];
    #pragma unroll
    for (int i = 0; i < 16; i++) acc[i] = bias;

    #pragma unroll
    for (int r = 0; r < 22; r++) {
        float v[7];
        #pragma unroll
        for (int kx = 0; kx < 7; kx++) v[kx] = tile[(ty0 + r)*70 + tx + kx];
        #pragma unroll
        for (int ky = 0; ky < 7; ky++) {
            int ro = r - ky;
            if (ro >= 0 && ro < 16) {
                #pragma unroll
                for (int kx = 0; kx < 7; kx++)
                    acc[ro] += wc[ky*7+kx] * v[kx];
            }
        }
    }

    __nv_bfloat16* outp = g_xfh + ((size_t)(s*BB+b)*CC + c)*HWP;
    #pragma unroll
    for (int i = 0; i < 16; i++)
        outp[(ty0 + i)*WW + tx] = __float2bfloat16(acc[i]);
}

// ---------------------------------------------------------------------------
// K2: qkv GEMM bf16 mma, BK=64, 3-stage ring / prefetch distance 2.
// ---------------------------------------------------------------------------
__global__ void __launch_bounds__(256, 2) qkv_tc_kernel()
{
    __shared__ __align__(16) __nv_bfloat16 sA[3][128*QST];   // A: 128 o x 64 c
    __shared__ __align__(16) __nv_bfloat16 sB[3][64*VST];    // B: 64 c x 128 n
    __shared__ float sred[128][2];

    int oBase = blockIdx.x * 128;
    int pTile = blockIdx.y;
    int pBase = pTile * 128;
    int s = blockIdx.z >> 3, b = blockIdx.z & 7;
    int sb = s*BB + b;

    const __nv_bfloat16* W = g_wqkv + (size_t)s*C3*CC;
    const float* qb = g_qb + s*C3;
    const __nv_bfloat16* X = g_xfh + (size_t)sb*CC*HWP;   // [c][n]

    int t = threadIdx.x;
    int wid = t >> 5, lane = t & 31;
    int warpM = wid >> 1, warpN = wid & 1;
    int mbw = warpM*32, nbw = warpN*64;
    int g = lane >> 2, q = lane & 3;

    uint32_t sA0 = smem_u32(sA[0]);
    uint32_t sB0 = smem_u32(sB[0]);
    const uint32_t ABUF = 128*QST*2;
    const uint32_t BBUF = 64*VST*2;

    int lrow = lane & 7, lmat = lane >> 3;
    uint32_t aoff = (uint32_t)((mbw + (lmat & 1)*8 + lrow)*QST + (lmat >> 1)*8) * 2;
    uint32_t boff = (uint32_t)(((lmat & 1)*8 + lrow)*VST + nbw + (lmat >> 1)*8) * 2;

    float acc[2][8][4] = {};

    auto stage = [&](int k0, int st) {
        uint32_t ab = sA0 + st*ABUF, bb = sB0 + st*BBUF;
        #pragma unroll
        for (int e = 0; e < 4; e++) {
            int c = t + e*256;
            int arow = c >> 3, agrp = c & 7;
            cpa16(ab + (uint32_t)(arow*QST + agrp*8)*2,
                  W + (size_t)(oBase + arow)*CC + k0 + agrp*8);
            int brow = c >> 4, bgrp = c & 15;
            cpa16(bb + (uint32_t)(brow*VST + bgrp*8)*2,
                  X + (size_t)(k0 + brow)*HWP + pBase + bgrp*8);
        }
    };

    stage(0, 0);  CPA_COMMIT();
    stage(64, 1); CPA_COMMIT();

    const int NIT = CC / 64;   // 4
    for (int it = 0; it < NIT; it++) {
        if (it < NIT-1) CPA_WAIT1(); else CPA_WAIT0();
        __syncthreads();
        if (it + 2 < NIT) { stage((it+2)*64, (it+2)%3); CPA_COMMIT(); }

        int st = it % 3;
        uint32_t Ab = sA0 + st*ABUF, Bb = sB0 + st*BBUF;
        #pragma unroll
        for (int ks = 0; ks < 4; ks++) {
            uint32_t af[2][4];
            ldsm_x4(Ab + aoff + ks*32,        af[0][0], af[0][1], af[0][2], af[0][3]);
            ldsm_x4(Ab + aoff + 2304 + ks*32, af[1][0], af[1][1], af[1][2], af[1][3]);
            #pragma unroll
            for (int p = 0; p < 4; p++) {
                uint32_t r0, r1, r2, r3;
                ldsm_x4_t(Bb + boff + ks*(16*VST*2) + p*32, r0, r1, r2, r3);
                mma_bf16(acc[0][2*p],   af[0], r0, r1);
                mma_bf16(acc[0][2*p+1], af[0], r2, r3);
                mma_bf16(acc[1][2*p],   af[1], r0, r1);
                mma_bf16(acc[1][2*p+1], af[1], r2, r3);
            }
        }
    }

    bool isV = (oBase >= 512);
    float rs[2][2] = {};

    __syncthreads();
    char* stg = (char*)sA[0];

    #pragma unroll
    for (int mt = 0; mt < 2; mt++) {
        int r0l = mbw + mt*16 + g;
        int r1l = r0l + 8;
        float sft0 = qb[oBase + r0l], sft1 = qb[oBase + r1l];
        #pragma unroll
        for (int nt = 0; nt < 8; nt++) {
            int col = nbw + nt*8 + q*2;
            float2 v0, v1;
            v0.x = gelu_f(acc[mt][nt][0] + sft0);
            v0.y = gelu_f(acc[mt][nt][1] + sft0);
            v1.x = gelu_f(acc[mt][nt][2] + sft1);
            v1.y = gelu_f(acc[mt][nt][3] + sft1);
            uint32_t p0, p1;
            if (isV) {
                __half2 h0 = __float22half2_rn(v0), h1 = __float22half2_rn(v1);
                p0 = *(uint32_t*)&h0; p1 = *(uint32_t*)&h1;
                rs[mt][0] += v0.x + v0.y;
                rs[mt][1] += v1.x + v1.y;
            } else {
                __nv_bfloat162 b0 = __float22bfloat162_rn(v0), b1 = __float22bfloat162_rn(v1);
                p0 = *(uint32_t*)&b0; p1 = *(uint32_t*)&b1;
                rs[mt][0] += v0.x*v0.x + v0.y*v0.y;
                rs[mt][1] += v1.x*v1.x + v1.y*v1.y;
            }
            *(uint32_t*)(stg + (r0l*SST + col)*2) = p0;
            *(uint32_t*)(stg + (r1l*SST + col)*2) = p1;
        }
    }

    #pragma unroll
    for (int mt = 0; mt < 2; mt++)
        #pragma unroll
        for (int rr = 0; rr < 2; rr++) {
            float v = rs[mt][rr];
            v += __shfl_xor_sync(0xffffffffu, v, 1);
            v += __shfl_xor_sync(0xffffffffu, v, 2);
            if (q == 0) sred[mbw + mt*16 + g + rr*8][warpN] = v;
        }
    __syncthreads();

    #pragma unroll
    for (int e = 0; e < 8; e++) {
        int c = t + e*256;
        int row = c >> 4, grp = c & 15;
        uint4 val = *(uint4*)(stg + (row*SST + grp*8)*2);
        if (isV)
            *(uint4*)(g_vh + ((size_t)sb*CC + (oBase - 512 + row))*HWP + pBase + grp*8) = val;
        else
            *(uint4*)(g_qk + ((size_t)sb*512 + oBase + row)*HWP + pBase + grp*8) = val;
    }

    if (t < 128) {
        float tot = sred[t][0] + sred[t][1];
        if (isV) g_vs_part[((size_t)pTile*16 + sb)*256 + (oBase - 512 + t)] = tot;
        else     g_ss_part[((size_t)pTile*16 + sb)*512 + (oBase + t)] = tot;
    }
}

// ---------------------------------------------------------------------------
// K4: attention logit partials via bf16 mma + ldmatrix
// ---------------------------------------------------------------------------
#define ANC 128
#define AST (ANC + 8)

__global__ void __launch_bounds__(256) attn_part_kernel() {
    int cx = blockIdx.x;
    int hb = blockIdx.y;
    int which = blockIdx.z;
    int h = hb & 3, b = hb >> 2;
    const __nv_bfloat16* Q = g_qk + ((size_t)(which*BB+b)*512 +       h*HDD)*HWP;
    const __nv_bfloat16* K = g_qk + ((size_t)((1-which)*BB+b)*512 + 256 + h*HDD)*HWP;

    __shared__ __align__(16) __nv_bfloat16 sQ[2][64*AST];
    __shared__ __align__(16) __nv_bfloat16 sK[2][64*AST];

    int t = threadIdx.x;
    int wid = t >> 5, lane = t & 31;
    int g = lane >> 2, q = lane & 3;
    int dBase = wid * 8;

    uint32_t sQb[2] = { smem_u32(sQ[0]), smem_u32(sQ[1]) };
    uint32_t sKb[2] = { smem_u32(sK[0]), smem_u32(sK[1]) };

    int lrow = lane & 7, lmat = lane >> 3;
    uint32_t qoff = (uint32_t)(((lmat & 1)*8 + lrow)*AST + (lmat >> 1)*8) * 2;
    uint32_t koff = (uint32_t)((dBase + lrow)*AST + lmat*8) * 2;

    auto stage = [&](int n0, int buf) {
        #pragma unroll
        for (int e = 0; e < 4; e++) {
            int c = t + e*256;
            int row = c >> 4, grp = c & 15;
            cpa16(sQb[buf] + (uint32_t)(row*AST + grp*8)*2, Q + (size_t)row*HWP + n0 + grp*8);
            cpa16(sKb[buf] + (uint32_t)(row*AST + grp*8)*2, K + (size_t)row*HWP + n0 + grp*8);
        }
    };

    float acc[4][4] = {};
    int n0base = cx * 1024;

    stage(n0base, 0);
    CPA_COMMIT();

    for (int st = 0; st < 8; st++) {
        int buf = st & 1;
        if (st + 1 < 8) { stage(n0base + (st+1)*ANC, buf ^ 1); CPA_COMMIT(); CPA_WAIT1(); }
        else CPA_WAIT0();
        __syncthreads();

        uint32_t Qb = sQb[buf], Kb = sKb[buf];
        #pragma unroll
        for (int ks2 = 0; ks2 < 4; ks2++) {
            uint32_t kb0, kb1, kb2, kb3;
            ldsm_x4(Kb + koff + ks2*64, kb0, kb1, kb2, kb3);
            #pragma unroll
            for (int half = 0; half < 2; half++) {
                uint32_t b0 = half ? kb2 : kb0;
                uint32_t b1 = half ? kb3 : kb1;
                #pragma unroll
                for (int mt = 0; mt < 4; mt++) {
                    uint32_t a[4];
                    ldsm_x4(Qb + qoff + mt*(16*AST*2) + ks2*64 + half*32,
                            a[0], a[1], a[2], a[3]);
                    mma_bf16(acc[mt], a, b0, b1);
                }
            }
        }
        __syncthreads();
    }

    float* P = g_lpart + (size_t)(((cx*2 + which)*BB + b)*NHH + h)*HDD*HDD;
    #pragma unroll
    for (int mt = 0; mt < 4; mt++) {
        float2 lo = { acc[mt][0], acc[mt][1] };
        float2 hi = { acc[mt][2], acc[mt][3] };
        *(float2*)(P + (mt*16 + g)*64 + dBase + 2*q) = lo;
        *(float2*)(P + (mt*16 + g + 8)*64 + dBase + 2*q) = hi;
    }
}

// ---------------------------------------------------------------------------
// K5: softmax over summed partials + SE-pool via A @ vmean (256 threads)
//     norms/vmean computed inline from per-pTile partials (finalize fused).
// ---------------------------------------------------------------------------
__global__ void __launch_bounds__(256) attn_soft_kernel() {
    int hb = blockIdx.x;
    int which = blockIdx.y;
    int h = hb & 3, b = hb >> 2;
    int t = threadIdx.x;
    int sbq = which*BB + b;        // stream of q (and v)
    int sbk = (1-which)*BB + b;    // stream of k

    __shared__ float S[64][65];
    __shared__ float rq[64], rk[64], vm[64];

    // fused finalize: reduce the 32 per-pTile partials for the 192 values we need
    if (t < 64) {
        int ch = h*64 + t;
        float ss = 0.0f;
        for (int p = 0; p < NPT; p++) ss += g_ss_part[((size_t)p*16 + sbq)*512 + ch];
        rq[t] = 1.0f / fmaxf(sqrtf(ss), 1e-12f);
    } else if (t < 128) {
        int ch = 256 + h*64 + (t - 64);
        float ss = 0.0f;
        for (int p = 0; p < NPT; p++) ss += g_ss_part[((size_t)p*16 + sbk)*512 + ch];
        rk[t - 64] = 1.0f / fmaxf(sqrtf(ss), 1e-12f);
    } else if (t < 192) {
        int ch = h*64 + (t - 128);
        float vs = 0.0f;
        for (int p = 0; p < NPT; p++) vs += g_vs_part[((size_t)p*16 + sbq)*256 + ch];
        vm[t - 128] = vs * (1.0f/HWP);
    }

    float vacc[16];
    {
        const float* P0 = g_lpart + (size_t)(((0*2 + which)*BB + b)*NHH + h)*HDD*HDD;
        #pragma unroll
        for (int j = 0; j < 16; j++) vacc[j] = P0[t + j*256];
    }
    #pragma unroll
    for (int cx = 1; cx < 4; cx++) {
        const float* P = g_lpart + (size_t)(((cx*2 + which)*BB + b)*NHH + h)*HDD*HDD;
        #pragma unroll
        for (int j = 0; j < 16; j++) vacc[j] += P[t + j*256];
    }
    #pragma unroll
    for (int j = 0; j < 16; j++) {
        int idx = t + j*256;
        S[idx >> 6][idx & 63] = vacc[j];
    }
    __syncthreads();

    if (t < 64) {
        float sc = 0.125f * rq[t];
        float m = -1e30f;
        #pragma unroll
        for (int d = 0; d < 64; d++) {
            float v = S[t][d] * sc * rk[d];
            S[t][d] = v;
            m = fmaxf(m, v);
        }
        float sum = 0.0f;
        #pragma unroll
        for (int d = 0; d < 64; d++) { float ev = expf(S[t][d] - m); S[t][d] = ev; sum += ev; }
        float inv = 1.0f / sum;

        float* ap = g_attn + (size_t)((sbq*NHH + h)*HDD + t)*HDD;
        float pool = 0.0f;
        #pragma unroll
        for (int d = 0; d < 64; d++) {
            float a = S[t][d] * inv;
            ap[d] = a;
            pool += a * vm[d];
        }
        g_pool[sbq*CC + h*64 + t] = pool;
    }
}

// ---------------------------------------------------------------------------
// K7: M = PO * diag(gate) * A_blk  -> fp16   (SE gate computed in-block)
// ---------------------------------------------------------------------------
__global__ void __launch_bounds__(256) mproj_kernel(
    const float* __restrict__ pw1, const float* __restrict__ pw2,
    const float* __restrict__ cw1, const float* __restrict__ cb1,
    const float* __restrict__ cw2, const float* __restrict__ cb2)
{
    int h = blockIdx.x, b = blockIdx.y, s = blockIdx.z;
    int sb = s*BB + b;
    const float* PO = s ? pw2 : pw1;
    const float* A  = g_attn + (size_t)((sb)*NHH + h)*HDD*HDD;
    int t = threadIdx.x;

    __shared__ float Ag[64][65];
    __shared__ float gsl[64];
    __shared__ float pm[256], ys[32];

    pm[t] = g_pool[sb*CC + t];
    for (int idx = t; idx < 4096; idx += 256)
        Ag[idx >> 6][idx & 63] = A[idx];
    __syncthreads();

    // SE gate: y = relu(W1 . pool + b1)
    if (t < 32) {
        float a = cb1[t];
        #pragma unroll 8
        for (int c = 0; c < 256; c++) a += cw1[t*256 + c]*pm[c];
        ys[t] = fmaxf(a, 0.0f);
    }
    __syncthreads();
    // gate for this head's 64 channels
    if (t < 64) {
        int ch = h*64 + t;
        float a = cb2[ch];
        #pragma unroll
        for (int r = 0; r < 32; r++) a += cw2[ch*32 + r]*ys[r];
        gsl[t] = 1.0f/(1.0f + expf(-a));
    }
    __syncthreads();

    float m[64];
    #pragma unroll
    for (int d = 0; d < 64; d++) m[d] = 0.0f;

    const float* po = PO + (size_t)t*CC + h*64;
    for (int c = 0; c < 64; c++) {
        float poc = po[c] * gsl[c];
        #pragma unroll
        for (int d = 0; d < 64; d++) m[d] += poc * Ag[c][d];
    }

    __half* Mp = g_Mh + (size_t)sb*CC*CC + (size_t)t*CC + h*64;
    #pragma unroll
    for (int d = 0; d < 64; d += 2)
        *(__half2*)(Mp + d) = __floats2half2_rn(m[d], m[d+1]);
}

// ---------------------------------------------------------------------------
// K8: out = M @ V + bias + residual  (fp16 mma; BK=64, 3-stage ring)
// ---------------------------------------------------------------------------
__global__ void __launch_bounds__(256, 2) mv_tc_kernel(
    const float* __restrict__ x1, const float* __restrict__ x2,
    const float* __restrict__ pb1, const float* __restrict__ pb2,
    float* __restrict__ out)
{
    __shared__ __align__(16) __half sM[3][128*QST];
    __shared__ __align__(16) __half sV[3][64*VST];

    int pBase = blockIdx.x * 128;
    int oBase = blockIdx.y * 128;
    int s = blockIdx.z >> 3, b = blockIdx.z & 7;
    int sb = s*BB + b;

    const __half* Mh = g_Mh + (size_t)sb*CC*CC;
    const __half* Vh = g_vh + (size_t)sb*CC*HWP;
    const float* pb  = s ? pb2 : pb1;
    const float* res = (s ? x2 : x1) + (size_t)b*CC*HWP;
    float*       Y   = out + ((size_t)sb)*CC*HWP;

    int t = threadIdx.x;
    int wid = t >> 5, lane = t & 31;
    int warpM = wid >> 1, warpN = wid & 1;
    int mbw = warpM*32, nbw = warpN*64;
    int g = lane >> 2, q = lane & 3;
    int lrow = lane & 7, lmat = lane >> 3;

    uint32_t sM0 = smem_u32(sM[0]);
    uint32_t sV0 = smem_u32(sV[0]);
    const uint32_t MBUF = 128*QST*2;
    const uint32_t VBUF = 64*VST*2;

    uint32_t aoff = (uint32_t)((mbw + (lmat & 1)*8 + lrow)*QST + (lmat >> 1)*8) * 2;
    uint32_t boff = (uint32_t)(((lmat & 1)*8 + lrow)*VST + nbw + (lmat >> 1)*8) * 2;

    float acc[2][8][4] = {};

    auto stage = [&](int k0, int st) {
        uint32_t ab = sM0 + st*MBUF, vb = sV0 + st*VBUF;
        #pragma unroll
        for (int e = 0; e < 4; e++) {
            int c = t + e*256;
            int mrow = c >> 3, mgrp = c & 7;
            cpa16(ab + (uint32_t)(mrow*QST + mgrp*8)*2,
                  Mh + (size_t)(oBase + mrow)*CC + k0 + mgrp*8);
            int vrow = c >> 4, vgrp = c & 15;
            cpa16(vb + (uint32_t)(vrow*VST + vgrp*8)*2,
                  Vh + (size_t)(k0 + vrow)*HWP + pBase + vgrp*8);
        }
    };

    stage(0, 0);  CPA_COMMIT();
    stage(64, 1); CPA_COMMIT();

    const int NIT = CC / 64;   // 4
    for (int it = 0; it < NIT; it++) {
        if (it < NIT-1) CPA_WAIT1(); else CPA_WAIT0();
        __syncthreads();
        if (it + 2 < NIT) { stage((it+2)*64, (it+2)%3); CPA_COMMIT(); }

        int st = it % 3;
        uint32_t Ab = sM0 + st*MBUF, Vb = sV0 + st*VBUF;
        #pragma unroll
        for (int ks = 0; ks < 4; ks++) {
            uint32_t af[2][4];
            ldsm_x4(Ab + aoff + ks*32,        af[0][0], af[0][1], af[0][2], af[0][3]);
            ldsm_x4(Ab + aoff + 2304 + ks*32, af[1][0], af[1][1], af[1][2], af[1][3]);
            #pragma unroll
            for (int p = 0; p < 4; p++) {
                uint32_t r0, r1, r2, r3;
                ldsm_x4_t(Vb + boff + ks*(16*VST*2) + p*32, r0, r1, r2, r3);
                mma_f16(acc[0][2*p],   af[0], r0, r1);
                mma_f16(acc[0][2*p+1], af[0], r2, r3);
                mma_f16(acc[1][2*p],   af[1], r0, r1);
                mma_f16(acc[1][2*p+1], af[1], r2, r3);
            }
        }
    }

    #pragma unroll
    for (int mt = 0; mt < 2; mt++) {
        int o0 = oBase + mbw + mt*16 + g;
        int o1 = o0 + 8;
        float bo0 = pb[o0], bo1 = pb[o1];
        float* y0 = Y + (size_t)o0*HWP + pBase + nbw + q*2;
        float* y1 = Y + (size_t)o1*HWP + pBase + nbw + q*2;
        const float* r0 = res + (size_t)o0*HWP + pBase + nbw + q*2;
        const float* r1 = res + (size_t)o1*HWP + pBase + nbw + q*2;
        #pragma unroll
        for (int nt = 0; nt < 8; nt++) {
            float2 rv0 = *(const float2*)(r0 + nt*8);
            float2 rv1 = *(const float2*)(r1 + nt*8);
            float2 v0, v1;
            v0.x = acc[mt][nt][0] + bo0 + rv0.x;
            v0.y = acc[mt][nt][1] + bo0 + rv0.y;
            v1.x = acc[mt][nt][2] + bo1 + rv1.x;
            v1.y = acc[mt][nt][3] + bo1 + rv1.y;
            *(float2*)(y0 + nt*8) = v0;
            *(float2*)(y1 + nt*8) = v1;
        }
    }
}

// ---------------------------------------------------------------------------
extern "C" void kernel_launch(void* const* d_in, const int* in_sizes, int n_in,
                              void* d_out, int out_size)
{
    const float* x1     = (const float*)d_in[0];
    const float* x2     = (const float*)d_in[1];
    const float* ms_w3  = (const float*)d_in[2];
    const float* ms_b3  = (const float*)d_in[3];
    const float* ms_w5  = (const float*)d_in[4];
    const float* ms_b5  = (const float*)d_in[5];
    const float* ms_w7  = (const float*)d_in[6];
    const float* ms_b7  = (const float*)d_in[7];
    const float* qkv1_w = (const float*)d_in[8];
    const float* qkv1_b = (const float*)d_in[9];
    const float* bn1_g  = (const float*)d_in[10];
    const float* bn1_b  = (const float*)d_in[11];
    const float* bn1_m  = (const float*)d_in[12];
    const float* bn1_v  = (const float*)d_in[13];
    const float* qkv2_w = (const float*)d_in[14];
    const float* qkv2_b = (const float*)d_in[15];
    const float* bn2_g  = (const float*)d_in[16];
    const float* bn2_b  = (const float*)d_in[17];
    const float* bn2_m  = (const float*)d_in[18];
    const float* bn2_v  = (const float*)d_in[19];
    const float* ca_w1  = (const float*)d_in[20];
    const float* ca_b1  = (const float*)d_in[21];
    const float* ca_w2  = (const float*)d_in[22];
    const float* ca_b2  = (const float*)d_in[23];
    const float* po1_w  = (const float*)d_in[24];
    const float* po1_b  = (const float*)d_in[25];
    const float* po2_w  = (const float*)d_in[26];
    const float* po2_b  = (const float*)d_in[27];
    float* out = (float*)d_out;

    convert_w_kernel<<<dim3(C3, 2), 256>>>(
        qkv1_w, qkv1_b, bn1_g, bn1_b, bn1_m, bn1_v,
        qkv2_w, qkv2_b, bn2_g, bn2_b, bn2_m, bn2_v);
    msconv_kernel<<<dim3(CC, BB, 2), 256>>>(x1, x2, ms_w3, ms_b3, ms_w5, ms_b5, ms_w7, ms_b7);
    qkv_tc_kernel<<<dim3(C3/128, NPT, 16), 256>>>();
    attn_part_kernel<<<dim3(4, NHH*BB, 2), 256>>>();
    attn_soft_kernel<<<dim3(NHH*BB, 2), 256>>>();
    mproj_kernel<<<dim3(NHH, BB, 2), 256>>>(po1_w, po2_w, ca_w1, ca_b1, ca_w2, ca_b2);
    mv_tc_kernel<<<dim3(HWP/128, CC/128, 16), 256>>>(x1, x2, po1_b, po2_b, out);
}

// round 16
// speedup vs baseline: 1.0885x; 1.0042x over previous
#include <cuda_runtime.h>
#include <cuda_bf16.h>
#include <cuda_fp16.h>
#include <math.h>
#include <cstdint>

#define BB  8
#define CC  256
#define HH  64
#define WW  64
#define HWP 4096
#define NHH 4
#define HDD 64
#define C3  768
#define NPT 32
#define NCX 8              // attn_part n-chunks

// ---- scratch (static device globals) ----
__device__ __nv_bfloat16  g_xfh[2ULL*BB*CC*HWP];   // msconv out, [c][n] bf16
__device__ __nv_bfloat16  g_wqkv[2ULL*C3*CC];      // BN-folded weights bf16
__device__ float          g_qb  [2ULL*C3];         // BN-folded bias
__device__ __nv_bfloat16  g_qk [2ULL*BB*512*HWP];
__device__ __half         g_vh [2ULL*BB*CC*HWP];
__device__ float g_ss_part[NPT*16*512];
__device__ float g_vs_part[NPT*16*256];
__device__ float g_lpart[(size_t)NCX*2*BB*NHH*HDD*HDD];
__device__ float g_attn [2*BB*NHH*HDD*HDD];
__device__ float g_pool [2*BB*CC];
__device__ __half g_Mh  [16ULL*CC*CC];

// ======================= helpers =======================
__device__ __forceinline__ uint32_t smem_u32(const void* p) {
    uint32_t a;
    asm("{ .reg .u64 t; cvta.to.shared.u64 t, %1; cvt.u32.u64 %0, t; }" : "=r"(a) : "l"(p));
    return a;
}
__device__ __forceinline__ void cpa16(uint32_t dst, const void* src) {
    asm volatile("cp.async.cg.shared.global [%0], [%1], 16;" :: "r"(dst), "l"(src));
}
#define CPA_COMMIT() asm volatile("cp.async.commit_group;" ::: "memory")
#define CPA_WAIT1()  asm volatile("cp.async.wait_group 1;" ::: "memory")
#define CPA_WAIT0()  asm volatile("cp.async.wait_group 0;" ::: "memory")

__device__ __forceinline__ void mma_bf16(float* d, const uint32_t* a, uint32_t b0, uint32_t b1) {
    asm volatile(
        "mma.sync.aligned.m16n8k16.row.col.f32.bf16.bf16.f32 "
        "{%0,%1,%2,%3}, {%4,%5,%6,%7}, {%8,%9}, {%0,%1,%2,%3};"
        : "+f"(d[0]), "+f"(d[1]), "+f"(d[2]), "+f"(d[3])
        : "r"(a[0]), "r"(a[1]), "r"(a[2]), "r"(a[3]), "r"(b0), "r"(b1));
}
__device__ __forceinline__ void mma_f16(float* d, const uint32_t* a, uint32_t b0, uint32_t b1) {
    asm volatile(
        "mma.sync.aligned.m16n8k16.row.col.f32.f16.f16.f32 "
        "{%0,%1,%2,%3}, {%4,%5,%6,%7}, {%8,%9}, {%0,%1,%2,%3};"
        : "+f"(d[0]), "+f"(d[1]), "+f"(d[2]), "+f"(d[3])
        : "r"(a[0]), "r"(a[1]), "r"(a[2]), "r"(a[3]), "r"(b0), "r"(b1));
}
__device__ __forceinline__ void ldsm_x4(uint32_t addr, uint32_t& r0, uint32_t& r1,
                                        uint32_t& r2, uint32_t& r3) {
    asm volatile("ldmatrix.sync.aligned.m8n8.x4.shared.b16 {%0,%1,%2,%3}, [%4];"
                 : "=r"(r0), "=r"(r1), "=r"(r2), "=r"(r3) : "r"(addr));
}
__device__ __forceinline__ void ldsm_x4_t(uint32_t addr, uint32_t& r0, uint32_t& r1,
                                          uint32_t& r2, uint32_t& r3) {
    asm volatile("ldmatrix.sync.aligned.m8n8.x4.trans.shared.b16 {%0,%1,%2,%3}, [%4];"
                 : "=r"(r0), "=r"(r1), "=r"(r2), "=r"(r3) : "r"(addr));
}
// fast GELU: tanh formulation with HW tanh.approx
__device__ __forceinline__ float gelu_f(float x) {
    float u = 0.7978845608028654f * fmaf(0.044715f * x, x * x, x);
    float th;
    asm("tanh.approx.f32 %0, %1;" : "=f"(th) : "f"(u));
    return 0.5f * x * (1.0f + th);
}

#define QST 72        // A smem row stride (elems): 144B
#define VST 136       // B/V smem row stride (elems): 272B, trans-ldmatrix friendly
#define SST 136       // qkv epilogue staging row stride (elems)

// ---------------------------------------------------------------------------
// K0a: fold BN into qkv weights + bias
// ---------------------------------------------------------------------------
__global__ void convert_w_kernel(
    const float* __restrict__ w1, const float* __restrict__ bq1,
    const float* __restrict__ g1, const float* __restrict__ be1,
    const float* __restrict__ m1, const float* __restrict__ v1,
    const float* __restrict__ w2, const float* __restrict__ bq2,
    const float* __restrict__ g2, const float* __restrict__ be2,
    const float* __restrict__ m2, const float* __restrict__ v2)
{
    int o = blockIdx.x, s = blockIdx.y;
    const float* W  = s ? w2  : w1;
    const float* bq = s ? bq2 : bq1;
    const float* bg = s ? g2  : g1;
    const float* bb = s ? be2 : be1;
    const float* bm = s ? m2  : m1;
    const float* bv = s ? v2  : v1;
    float scl = bg[o] * rsqrtf(bv[o] + 1e-5f);
    int c = threadIdx.x;
    g_wqkv[(size_t)s*C3*CC + (size_t)o*CC + c] = __float2bfloat16(W[(size_t)o*CC + c] * scl);
    if (c == 0)
        g_qb[s*C3 + o] = bq[o]*scl + bb[o] - bm[o]*scl;
}

// ---------------------------------------------------------------------------
// K1: fused multiscale depthwise conv; writes bf16 [c][n]
// ---------------------------------------------------------------------------
__global__ void msconv_kernel(const float* __restrict__ x1, const float* __restrict__ x2,
                              const float* __restrict__ w3, const float* __restrict__ b3,
                              const float* __restrict__ w5, const float* __restrict__ b5,
                              const float* __restrict__ w7, const float* __restrict__ b7)
{
    int c = blockIdx.x, b = blockIdx.y, s = blockIdx.z;
    const float* xin = (s ? x2 : x1) + ((size_t)b*CC + c)*HWP;

    __shared__ float tile[70*70];
    __shared__ float wc[49];
    int t = threadIdx.x;

    if (t < 49) {
        int ky = t / 7, kx = t % 7;
        float w = w7[c*49 + t];
        if (ky >= 1 && ky <= 5 && kx >= 1 && kx <= 5) w += w5[c*25 + (ky-1)*5 + (kx-1)];
        if (ky >= 2 && ky <= 4 && kx >= 2 && kx <= 4) w += w3[c*9  + (ky-2)*3 + (kx-2)];
        wc[t] = w * (1.0f/3.0f);
    }
    for (int i = t; i < 70*70; i += 256) {
        int ty = i / 70, tx = i % 70;
        int gy = ty - 3, gx = tx - 3;
        tile[i] = (gy >= 0 && gy < HH && gx >= 0 && gx < WW) ? xin[gy*WW + gx] : 0.0f;
    }
    __syncthreads();

    int tx = t & 63;
    int ty0 = (t >> 6) * 16;
    float bias = (b3[c] + b5[c] + b7[c]) * (1.0f/3.0f);

    float acc[16];
    #pragma unroll
    for (int i = 0; i < 16; i++) acc[i] = bias;

    #pragma unroll
    for (int r = 0; r < 22; r++) {
        float v[7];
        #pragma unroll
        for (int kx = 0; kx < 7; kx++) v[kx] = tile[(ty0 + r)*70 + tx + kx];
        #pragma unroll
        for (int ky = 0; ky < 7; ky++) {
            int ro = r - ky;
            if (ro >= 0 && ro < 16) {
                #pragma unroll
                for (int kx = 0; kx < 7; kx++)
                    acc[ro] += wc[ky*7+kx] * v[kx];
            }
        }
    }

    __nv_bfloat16* outp = g_xfh + ((size_t)(s*BB+b)*CC + c)*HWP;
    #pragma unroll
    for (int i = 0; i < 16; i++)
        outp[(ty0 + i)*WW + tx] = __float2bfloat16(acc[i]);
}

// ---------------------------------------------------------------------------
// K2: qkv GEMM bf16 mma, BK=64, 3-stage ring / prefetch distance 2.
// ---------------------------------------------------------------------------
__global__ void __launch_bounds__(256, 2) qkv_tc_kernel()
{
    __shared__ __align__(16) __nv_bfloat16 sA[3][128*QST];   // A: 128 o x 64 c
    __shared__ __align__(16) __nv_bfloat16 sB[3][64*VST];    // B: 64 c x 128 n
    __shared__ float sred[128][2];

    int oBase = blockIdx.x * 128;
    int pTile = blockIdx.y;
    int pBase = pTile * 128;
    int s = blockIdx.z >> 3, b = blockIdx.z & 7;
    int sb = s*BB + b;

    const __nv_bfloat16* W = g_wqkv + (size_t)s*C3*CC;
    const float* qb = g_qb + s*C3;
    const __nv_bfloat16* X = g_xfh + (size_t)sb*CC*HWP;   // [c][n]

    int t = threadIdx.x;
    int wid = t >> 5, lane = t & 31;
    int warpM = wid >> 1, warpN = wid & 1;
    int mbw = warpM*32, nbw = warpN*64;
    int g = lane >> 2, q = lane & 3;

    uint32_t sA0 = smem_u32(sA[0]);
    uint32_t sB0 = smem_u32(sB[0]);
    const uint32_t ABUF = 128*QST*2;
    const uint32_t BBUF = 64*VST*2;

    int lrow = lane & 7, lmat = lane >> 3;
    uint32_t aoff = (uint32_t)((mbw + (lmat & 1)*8 + lrow)*QST + (lmat >> 1)*8) * 2;
    uint32_t boff = (uint32_t)(((lmat & 1)*8 + lrow)*VST + nbw + (lmat >> 1)*8) * 2;

    float acc[2][8][4] = {};

    auto stage = [&](int k0, int st) {
        uint32_t ab = sA0 + st*ABUF, bb = sB0 + st*BBUF;
        #pragma unroll
        for (int e = 0; e < 4; e++) {
            int c = t + e*256;
            int arow = c >> 3, agrp = c & 7;
            cpa16(ab + (uint32_t)(arow*QST + agrp*8)*2,
                  W + (size_t)(oBase + arow)*CC + k0 + agrp*8);
            int brow = c >> 4, bgrp = c & 15;
            cpa16(bb + (uint32_t)(brow*VST + bgrp*8)*2,
                  X + (size_t)(k0 + brow)*HWP + pBase + bgrp*8);
        }
    };

    stage(0, 0);  CPA_COMMIT();
    stage(64, 1); CPA_COMMIT();

    const int NIT = CC / 64;   // 4
    for (int it = 0; it < NIT; it++) {
        if (it < NIT-1) CPA_WAIT1(); else CPA_WAIT0();
        __syncthreads();
        if (it + 2 < NIT) { stage((it+2)*64, (it+2)%3); CPA_COMMIT(); }

        int st = it % 3;
        uint32_t Ab = sA0 + st*ABUF, Bb = sB0 + st*BBUF;
        #pragma unroll
        for (int ks = 0; ks < 4; ks++) {
            uint32_t af[2][4];
            ldsm_x4(Ab + aoff + ks*32,        af[0][0], af[0][1], af[0][2], af[0][3]);
            ldsm_x4(Ab + aoff + 2304 + ks*32, af[1][0], af[1][1], af[1][2], af[1][3]);
            #pragma unroll
            for (int p = 0; p < 4; p++) {
                uint32_t r0, r1, r2, r3;
                ldsm_x4_t(Bb + boff + ks*(16*VST*2) + p*32, r0, r1, r2, r3);
                mma_bf16(acc[0][2*p],   af[0], r0, r1);
                mma_bf16(acc[0][2*p+1], af[0], r2, r3);
                mma_bf16(acc[1][2*p],   af[1], r0, r1);
                mma_bf16(acc[1][2*p+1], af[1], r2, r3);
            }
        }
    }

    bool isV = (oBase >= 512);
    float rs[2][2] = {};

    __syncthreads();
    char* stg = (char*)sA[0];

    #pragma unroll
    for (int mt = 0; mt < 2; mt++) {
        int r0l = mbw + mt*16 + g;
        int r1l = r0l + 8;
        float sft0 = qb[oBase + r0l], sft1 = qb[oBase + r1l];
        #pragma unroll
        for (int nt = 0; nt < 8; nt++) {
            int col = nbw + nt*8 + q*2;
            float2 v0, v1;
            v0.x = gelu_f(acc[mt][nt][0] + sft0);
            v0.y = gelu_f(acc[mt][nt][1] + sft0);
            v1.x = gelu_f(acc[mt][nt][2] + sft1);
            v1.y = gelu_f(acc[mt][nt][3] + sft1);
            uint32_t p0, p1;
            if (isV) {
                __half2 h0 = __float22half2_rn(v0), h1 = __float22half2_rn(v1);
                p0 = *(uint32_t*)&h0; p1 = *(uint32_t*)&h1;
                rs[mt][0] += v0.x + v0.y;
                rs[mt][1] += v1.x + v1.y;
            } else {
                __nv_bfloat162 b0 = __float22bfloat162_rn(v0), b1 = __float22bfloat162_rn(v1);
                p0 = *(uint32_t*)&b0; p1 = *(uint32_t*)&b1;
                rs[mt][0] += v0.x*v0.x + v0.y*v0.y;
                rs[mt][1] += v1.x*v1.x + v1.y*v1.y;
            }
            *(uint32_t*)(stg + (r0l*SST + col)*2) = p0;
            *(uint32_t*)(stg + (r1l*SST + col)*2) = p1;
        }
    }

    #pragma unroll
    for (int mt = 0; mt < 2; mt++)
        #pragma unroll
        for (int rr = 0; rr < 2; rr++) {
            float v = rs[mt][rr];
            v += __shfl_xor_sync(0xffffffffu, v, 1);
            v += __shfl_xor_sync(0xffffffffu, v, 2);
            if (q == 0) sred[mbw + mt*16 + g + rr*8][warpN] = v;
        }
    __syncthreads();

    #pragma unroll
    for (int e = 0; e < 8; e++) {
        int c = t + e*256;
        int row = c >> 4, grp = c & 15;
        uint4 val = *(uint4*)(stg + (row*SST + grp*8)*2);
        if (isV)
            *(uint4*)(g_vh + ((size_t)sb*CC + (oBase - 512 + row))*HWP + pBase + grp*8) = val;
        else
            *(uint4*)(g_qk + ((size_t)sb*512 + oBase + row)*HWP + pBase + grp*8) = val;
    }

    if (t < 128) {
        float tot = sred[t][0] + sred[t][1];
        if (isV) g_vs_part[((size_t)pTile*16 + sb)*256 + (oBase - 512 + t)] = tot;
        else     g_ss_part[((size_t)pTile*16 + sb)*512 + (oBase + t)] = tot;
    }
}

// ---------------------------------------------------------------------------
// K4: attention logit partials via bf16 mma + ldmatrix (8 chunks of 512 cols)
// ---------------------------------------------------------------------------
#define ANC 128
#define AST (ANC + 8)

__global__ void __launch_bounds__(256) attn_part_kernel() {
    int cx = blockIdx.x;               // 0..NCX-1
    int hb = blockIdx.y;
    int which = blockIdx.z;
    int h = hb & 3, b = hb >> 2;
    const __nv_bfloat16* Q = g_qk + ((size_t)(which*BB+b)*512 +       h*HDD)*HWP;
    const __nv_bfloat16* K = g_qk + ((size_t)((1-which)*BB+b)*512 + 256 + h*HDD)*HWP;

    __shared__ __align__(16) __nv_bfloat16 sQ[2][64*AST];
    __shared__ __align__(16) __nv_bfloat16 sK[2][64*AST];

    int t = threadIdx.x;
    int wid = t >> 5, lane = t & 31;
    int g = lane >> 2, q = lane & 3;
    int dBase = wid * 8;

    uint32_t sQb[2] = { smem_u32(sQ[0]), smem_u32(sQ[1]) };
    uint32_t sKb[2] = { smem_u32(sK[0]), smem_u32(sK[1]) };

    int lrow = lane & 7, lmat = lane >> 3;
    uint32_t qoff = (uint32_t)(((lmat & 1)*8 + lrow)*AST + (lmat >> 1)*8) * 2;
    uint32_t koff = (uint32_t)((dBase + lrow)*AST + lmat*8) * 2;

    auto stage = [&](int n0, int buf) {
        #pragma unroll
        for (int e = 0; e < 4; e++) {
            int c = t + e*256;
            int row = c >> 4, grp = c & 15;
            cpa16(sQb[buf] + (uint32_t)(row*AST + grp*8)*2, Q + (size_t)row*HWP + n0 + grp*8);
            cpa16(sKb[buf] + (uint32_t)(row*AST + grp*8)*2, K + (size_t)row*HWP + n0 + grp*8);
        }
    };

    float acc[4][4] = {};
    int n0base = cx * (HWP / NCX);
    const int NST = (HWP / NCX) / ANC;   // 4

    stage(n0base, 0);
    CPA_COMMIT();

    for (int st = 0; st < NST; st++) {
        int buf = st & 1;
        if (st + 1 < NST) { stage(n0base + (st+1)*ANC, buf ^ 1); CPA_COMMIT(); CPA_WAIT1(); }
        else CPA_WAIT0();
        __syncthreads();

        uint32_t Qb = sQb[buf], Kb = sKb[buf];
        #pragma unroll
        for (int ks2 = 0; ks2 < 4; ks2++) {
            uint32_t kb0, kb1, kb2, kb3;
            ldsm_x4(Kb + koff + ks2*64, kb0, kb1, kb2, kb3);
            #pragma unroll
            for (int half = 0; half < 2; half++) {
                uint32_t b0 = half ? kb2 : kb0;
                uint32_t b1 = half ? kb3 : kb1;
                #pragma unroll
                for (int mt = 0; mt < 4; mt++) {
                    uint32_t a[4];
                    ldsm_x4(Qb + qoff + mt*(16*AST*2) + ks2*64 + half*32,
                            a[0], a[1], a[2], a[3]);
                    mma_bf16(acc[mt], a, b0, b1);
                }
            }
        }
        __syncthreads();
    }

    float* P = g_lpart + (size_t)(((cx*2 + which)*BB + b)*NHH + h)*HDD*HDD;
    #pragma unroll
    for (int mt = 0; mt < 4; mt++) {
        float2 lo = { acc[mt][0], acc[mt][1] };
        float2 hi = { acc[mt][2], acc[mt][3] };
        *(float2*)(P + (mt*16 + g)*64 + dBase + 2*q) = lo;
        *(float2*)(P + (mt*16 + g + 8)*64 + dBase + 2*q) = hi;
    }
}

// ---------------------------------------------------------------------------
// K5: softmax over summed partials + SE-pool via A @ vmean (256 threads)
//     norms/vmean computed inline from per-pTile partials.
// ---------------------------------------------------------------------------
__global__ void __launch_bounds__(256) attn_soft_kernel() {
    int hb = blockIdx.x;
    int which = blockIdx.y;
    int h = hb & 3, b = hb >> 2;
    int t = threadIdx.x;
    int sbq = which*BB + b;
    int sbk = (1-which)*BB + b;

    __shared__ float S[64][65];
    __shared__ float rq[64], rk[64], vm[64];

    if (t < 64) {
        int ch = h*64 + t;
        float ss = 0.0f;
        for (int p = 0; p < NPT; p++) ss += g_ss_part[((size_t)p*16 + sbq)*512 + ch];
        rq[t] = 1.0f / fmaxf(sqrtf(ss), 1e-12f);
    } else if (t < 128) {
        int ch = 256 + h*64 + (t - 64);
        float ss = 0.0f;
        for (int p = 0; p < NPT; p++) ss += g_ss_part[((size_t)p*16 + sbk)*512 + ch];
        rk[t - 64] = 1.0f / fmaxf(sqrtf(ss), 1e-12f);
    } else if (t < 192) {
        int ch = h*64 + (t - 128);
        float vs = 0.0f;
        for (int p = 0; p < NPT; p++) vs += g_vs_part[((size_t)p*16 + sbq)*256 + ch];
        vm[t - 128] = vs * (1.0f/HWP);
    }

    float vacc[16];
    {
        const float* P0 = g_lpart + (size_t)(((0*2 + which)*BB + b)*NHH + h)*HDD*HDD;
        #pragma unroll
        for (int j = 0; j < 16; j++) vacc[j] = P0[t + j*256];
    }
    #pragma unroll
    for (int cx = 1; cx < NCX; cx++) {
        const float* P = g_lpart + (size_t)(((cx*2 + which)*BB + b)*NHH + h)*HDD*HDD;
        #pragma unroll
        for (int j = 0; j < 16; j++) vacc[j] += P[t + j*256];
    }
    #pragma unroll
    for (int j = 0; j < 16; j++) {
        int idx = t + j*256;
        S[idx >> 6][idx & 63] = vacc[j];
    }
    __syncthreads();

    if (t < 64) {
        float sc = 0.125f * rq[t];
        float m = -1e30f;
        #pragma unroll
        for (int d = 0; d < 64; d++) {
            float v = S[t][d] * sc * rk[d];
            S[t][d] = v;
            m = fmaxf(m, v);
        }
        float sum = 0.0f;
        #pragma unroll
        for (int d = 0; d < 64; d++) { float ev = expf(S[t][d] - m); S[t][d] = ev; sum += ev; }
        float inv = 1.0f / sum;

        float* ap = g_attn + (size_t)((sbq*NHH + h)*HDD + t)*HDD;
        float pool = 0.0f;
        #pragma unroll
        for (int d = 0; d < 64; d++) {
            float a = S[t][d] * inv;
            ap[d] = a;
            pool += a * vm[d];
        }
        g_pool[sbq*CC + h*64 + t] = pool;
    }
}

// ---------------------------------------------------------------------------
// K7: M = PO * diag(gate) * A_blk  -> fp16   (SE gate computed in-block)
// ---------------------------------------------------------------------------
__global__ void __launch_bounds__(256) mproj_kernel(
    const float* __restrict__ pw1, const float* __restrict__ pw2,
    const float* __restrict__ cw1, const float* __restrict__ cb1,
    const float* __restrict__ cw2, const float* __restrict__ cb2)
{
    int h = blockIdx.x, b = blockIdx.y, s = blockIdx.z;
    int sb = s*BB + b;
    const float* PO = s ? pw2 : pw1;
    const float* A  = g_attn + (size_t)((sb)*NHH + h)*HDD*HDD;
    int t = threadIdx.x;

    __shared__ float Ag[64][65];
    __shared__ float gsl[64];
    __shared__ float pm[256], ys[32];

    pm[t] = g_pool[sb*CC + t];
    for (int idx = t; idx < 4096; idx += 256)
        Ag[idx >> 6][idx & 63] = A[idx];
    __syncthreads();

    if (t < 32) {
        float a = cb1[t];
        #pragma unroll 8
        for (int c = 0; c < 256; c++) a += cw1[t*256 + c]*pm[c];
        ys[t] = fmaxf(a, 0.0f);
    }
    __syncthreads();
    if (t < 64) {
        int ch = h*64 + t;
        float a = cb2[ch];
        #pragma unroll
        for (int r = 0; r < 32; r++) a += cw2[ch*32 + r]*ys[r];
        gsl[t] = 1.0f/(1.0f + expf(-a));
    }
    __syncthreads();

    float m[64];
    #pragma unroll
    for (int d = 0; d < 64; d++) m[d] = 0.0f;

    const float* po = PO + (size_t)t*CC + h*64;
    for (int c = 0; c < 64; c++) {
        float poc = po[c] * gsl[c];
        #pragma unroll
        for (int d = 0; d < 64; d++) m[d] += poc * Ag[c][d];
    }

    __half* Mp = g_Mh + (size_t)sb*CC*CC + (size_t)t*CC + h*64;
    #pragma unroll
    for (int d = 0; d < 64; d += 2)
        *(__half2*)(Mp + d) = __floats2half2_rn(m[d], m[d+1]);
}

// ---------------------------------------------------------------------------
// K8: out = M @ V + bias + residual  (fp16 mma; BK=64, 3-stage ring)
// ---------------------------------------------------------------------------
__global__ void __launch_bounds__(256, 2) mv_tc_kernel(
    const float* __restrict__ x1, const float* __restrict__ x2,
    const float* __restrict__ pb1, const float* __restrict__ pb2,
    float* __restrict__ out)
{
    __shared__ __align__(16) __half sM[3][128*QST];
    __shared__ __align__(16) __half sV[3][64*VST];

    int pBase = blockIdx.x * 128;
    int oBase = blockIdx.y * 128;
    int s = blockIdx.z >> 3, b = blockIdx.z & 7;
    int sb = s*BB + b;

    const __half* Mh = g_Mh + (size_t)sb*CC*CC;
    const __half* Vh = g_vh + (size_t)sb*CC*HWP;
    const float* pb  = s ? pb2 : pb1;
    const float* res = (s ? x2 : x1) + (size_t)b*CC*HWP;
    float*       Y   = out + ((size_t)sb)*CC*HWP;

    int t = threadIdx.x;
    int wid = t >> 5, lane = t & 31;
    int warpM = wid >> 1, warpN = wid & 1;
    int mbw = warpM*32, nbw = warpN*64;
    int g = lane >> 2, q = lane & 3;
    int lrow = lane & 7, lmat = lane >> 3;

    uint32_t sM0 = smem_u32(sM[0]);
    uint32_t sV0 = smem_u32(sV[0]);
    const uint32_t MBUF = 128*QST*2;
    const uint32_t VBUF = 64*VST*2;

    uint32_t aoff = (uint32_t)((mbw + (lmat & 1)*8 + lrow)*QST + (lmat >> 1)*8) * 2;
    uint32_t boff = (uint32_t)(((lmat & 1)*8 + lrow)*VST + nbw + (lmat >> 1)*8) * 2;

    float acc[2][8][4] = {};

    auto stage = [&](int k0, int st) {
        uint32_t ab = sM0 + st*MBUF, vb = sV0 + st*VBUF;
        #pragma unroll
        for (int e = 0; e < 4; e++) {
            int c = t + e*256;
            int mrow = c >> 3, mgrp = c & 7;
            cpa16(ab + (uint32_t)(mrow*QST + mgrp*8)*2,
                  Mh + (size_t)(oBase + mrow)*CC + k0 + mgrp*8);
            int vrow = c >> 4, vgrp = c & 15;
            cpa16(vb + (uint32_t)(vrow*VST + vgrp*8)*2,
                  Vh + (size_t)(k0 + vrow)*HWP + pBase + vgrp*8);
        }
    };

    stage(0, 0);  CPA_COMMIT();
    stage(64, 1); CPA_COMMIT();

    const int NIT = CC / 64;   // 4
    for (int it = 0; it < NIT; it++) {
        if (it < NIT-1) CPA_WAIT1(); else CPA_WAIT0();
        __syncthreads();
        if (it + 2 < NIT) { stage((it+2)*64, (it+2)%3); CPA_COMMIT(); }

        int st = it % 3;
        uint32_t Ab = sM0 + st*MBUF, Vb = sV0 + st*VBUF;
        #pragma unroll
        for (int ks = 0; ks < 4; ks++) {
            uint32_t af[2][4];
            ldsm_x4(Ab + aoff + ks*32,        af[0][0], af[0][1], af[0][2], af[0][3]);
            ldsm_x4(Ab + aoff + 2304 + ks*32, af[1][0], af[1][1], af[1][2], af[1][3]);
            #pragma unroll
            for (int p = 0; p < 4; p++) {
                uint32_t r0, r1, r2, r3;
                ldsm_x4_t(Vb + boff + ks*(16*VST*2) + p*32, r0, r1, r2, r3);
                mma_f16(acc[0][2*p],   af[0], r0, r1);
                mma_f16(acc[0][2*p+1], af[0], r2, r3);
                mma_f16(acc[1][2*p],   af[1], r0, r1);
                mma_f16(acc[1][2*p+1], af[1], r2, r3);
            }
        }
    }

    #pragma unroll
    for (int mt = 0; mt < 2; mt++) {
        int o0 = oBase + mbw + mt*16 + g;
        int o1 = o0 + 8;
        float bo0 = pb[o0], bo1 = pb[o1];
        float* y0 = Y + (size_t)o0*HWP + pBase + nbw + q*2;
        float* y1 = Y + (size_t)o1*HWP + pBase + nbw + q*2;
        const float* r0 = res + (size_t)o0*HWP + pBase + nbw + q*2;
        const float* r1 = res + (size_t)o1*HWP + pBase + nbw + q*2;
        #pragma unroll
        for (int nt = 0; nt < 8; nt++) {
            float2 rv0 = *(const float2*)(r0 + nt*8);
            float2 rv1 = *(const float2*)(r1 + nt*8);
            float2 v0, v1;
            v0.x = acc[mt][nt][0] + bo0 + rv0.x;
            v0.y = acc[mt][nt][1] + bo0 + rv0.y;
            v1.x = acc[mt][nt][2] + bo1 + rv1.x;
            v1.y = acc[mt][nt][3] + bo1 + rv1.y;
            *(float2*)(y0 + nt*8) = v0;
            *(float2*)(y1 + nt*8) = v1;
        }
    }
}

// ---------------------------------------------------------------------------
extern "C" void kernel_launch(void* const* d_in, const int* in_sizes, int n_in,
                              void* d_out, int out_size)
{
    const float* x1     = (const float*)d_in[0];
    const float* x2     = (const float*)d_in[1];
    const float* ms_w3  = (const float*)d_in[2];
    const float* ms_b3  = (const float*)d_in[3];
    const float* ms_w5  = (const float*)d_in[4];
    const float* ms_b5  = (const float*)d_in[5];
    const float* ms_w7  = (const float*)d_in[6];
    const float* ms_b7  = (const float*)d_in[7];
    const float* qkv1_w = (const float*)d_in[8];
    const float* qkv1_b = (const float*)d_in[9];
    const float* bn1_g  = (const float*)d_in[10];
    const float* bn1_b  = (const float*)d_in[11];
    const float* bn1_m  = (const float*)d_in[12];
    const float* bn1_v  = (const float*)d_in[13];
    const float* qkv2_w = (const float*)d_in[14];
    const float* qkv2_b = (const float*)d_in[15];
    const float* bn2_g  = (const float*)d_in[16];
    const float* bn2_b  = (const float*)d_in[17];
    const float* bn2_m  = (const float*)d_in[18];
    const float* bn2_v  = (const float*)d_in[19];
    const float* ca_w1  = (const float*)d_in[20];
    const float* ca_b1  = (const float*)d_in[21];
    const float* ca_w2  = (const float*)d_in[22];
    const float* ca_b2  = (const float*)d_in[23];
    const float* po1_w  = (const float*)d_in[24];
    const float* po1_b  = (const float*)d_in[25];
    const float* po2_w  = (const float*)d_in[26];
    const float* po2_b  = (const float*)d_in[27];
    float* out = (float*)d_out;

    convert_w_kernel<<<dim3(C3, 2), 256>>>(
        qkv1_w, qkv1_b, bn1_g, bn1_b, bn1_m, bn1_v,
        qkv2_w, qkv2_b, bn2_g, bn2_b, bn2_m, bn2_v);
    msconv_kernel<<<dim3(CC, BB, 2), 256>>>(x1, x2, ms_w3, ms_b3, ms_w5, ms_b5, ms_w7, ms_b7);
    qkv_tc_kernel<<<dim3(C3/128, NPT, 16), 256>>>();
    attn_part_kernel<<<dim3(NCX, NHH*BB, 2), 256>>>();
    attn_soft_kernel<<<dim3(NHH*BB, 2), 256>>>();
    mproj_kernel<<<dim3(NHH, BB, 2), 256>>>(po1_w, po2_w, ca_w1, ca_b1, ca_w2, ca_b2);
    mv_tc_kernel<<<dim3(HWP/128, CC/128, 16), 256>>>(x1, x2, po1_b, po2_b, out);
}